// round 9
// baseline (speedup 1.0000x reference)
#include <cuda_runtime.h>
#include <cuda_bf16.h>
#include <math.h>
#include <stdint.h>

#define MTOT 8192      // 2*4096 rows
#define NDIM 512
#define SEQ  4096
#define DH   64
#define NT   (SEQ / 128)

// scratch (allocation-free rule -> device globals)
__device__ __nv_bfloat16 g_xb [MTOT * NDIM];
__device__ __nv_bfloat16 g_Wqb[NDIM * NDIM];
__device__ __nv_bfloat16 g_Wkb[NDIM * NDIM];
__device__ __nv_bfloat16 g_Wvb[NDIM * NDIM];
__device__ __nv_bfloat16 g_Wob[NDIM * NDIM];
__device__ uint8_t       g_Q8 [MTOT * NDIM];   // e4m3, unscaled
__device__ uint8_t       g_K8 [MTOT * NDIM];   // e4m3
__device__ __nv_bfloat16 g_V  [MTOT * NDIM];
__device__ __nv_bfloat16 g_AO [MTOT * NDIM];

// ---------------------------------------------------------------------------
// helpers
// ---------------------------------------------------------------------------
static __device__ __forceinline__ uint32_t s2u(const void* p) {
    uint32_t a;
    asm("{ .reg .u64 t; cvta.to.shared.u64 t, %1; cvt.u32.u64 %0, t; }"
        : "=r"(a) : "l"(p));
    return a;
}
static __device__ __forceinline__ uint32_t packbf(float lo, float hi) {
    uint32_t r;
    asm("cvt.rn.bf16x2.f32 %0, %1, %2;" : "=r"(r) : "f"(hi), "f"(lo));
    return r;
}
static __device__ __forceinline__ uint16_t packf8(float lo, float hi) {
    uint16_t r;
    asm("cvt.rn.satfinite.e4m3x2.f32 %0, %1, %2;" : "=h"(r) : "f"(hi), "f"(lo));
    return r;
}
static __device__ __forceinline__ void cpa16(uint32_t dst, const void* src) {
    asm volatile("cp.async.cg.shared.global [%0], [%1], 16;"
                 :: "r"(dst), "l"(src));
}
static __device__ __forceinline__ void cpa_commit() {
    asm volatile("cp.async.commit_group;" ::: "memory");
}
static __device__ __forceinline__ void cpa_wait0() {
    asm volatile("cp.async.wait_group 0;" ::: "memory");
}

#define MMA_BF16(c, a, b0, b1)                                              \
    asm volatile(                                                           \
        "mma.sync.aligned.m16n8k16.row.col.f32.bf16.bf16.f32 "              \
        "{%0,%1,%2,%3},{%4,%5,%6,%7},{%8,%9},{%0,%1,%2,%3};"                \
        : "+f"((c)[0]), "+f"((c)[1]), "+f"((c)[2]), "+f"((c)[3])            \
        : "r"((a)[0]), "r"((a)[1]), "r"((a)[2]), "r"((a)[3]),               \
          "r"(b0), "r"(b1))

#define MMA_FP8(c, a, b0, b1)                                               \
    asm volatile(                                                           \
        "mma.sync.aligned.m16n8k32.row.col.f32.e4m3.e4m3.f32 "              \
        "{%0,%1,%2,%3},{%4,%5,%6,%7},{%8,%9},{%0,%1,%2,%3};"                \
        : "+f"((c)[0]), "+f"((c)[1]), "+f"((c)[2]), "+f"((c)[3])            \
        : "r"((a)[0]), "r"((a)[1]), "r"((a)[2]), "r"((a)[3]),               \
          "r"(b0), "r"(b1))

#define LDSM_X4_T(r0, r1, r2, r3, addr)                                     \
    asm volatile(                                                           \
        "ldmatrix.sync.aligned.m8n8.x4.trans.shared.b16 {%0,%1,%2,%3}, [%4];"\
        : "=r"(r0), "=r"(r1), "=r"(r2), "=r"(r3) : "r"(addr))

// ---------------------------------------------------------------------------
// fp32 -> bf16 convert pre-pass (x; and the 4 weights in one launch)
// ---------------------------------------------------------------------------
__global__ void __launch_bounds__(256) cvt_kernel(const float* __restrict__ s,
                                                  __nv_bfloat16* __restrict__ d)
{
    const int i = (blockIdx.x * 256 + threadIdx.x) * 4;
    const float4 v = *(const float4*)(s + i);
    *(uint32_t*)(d + i)     = packbf(v.x, v.y);
    *(uint32_t*)(d + i + 2) = packbf(v.z, v.w);
}

__global__ void __launch_bounds__(256) cvtw_kernel(const float* __restrict__ wq,
                                                   const float* __restrict__ wk,
                                                   const float* __restrict__ wv,
                                                   const float* __restrict__ wo)
{
    const float* s;
    __nv_bfloat16* d;
    switch (blockIdx.z) {
        case 0:  s = wq; d = g_Wqb; break;
        case 1:  s = wk; d = g_Wkb; break;
        case 2:  s = wv; d = g_Wvb; break;
        default: s = wo; d = g_Wob; break;
    }
    const int i = (blockIdx.x * 256 + threadIdx.x) * 4;
    const float4 v = *(const float4*)(s + i);
    *(uint32_t*)(d + i)     = packbf(v.x, v.y);
    *(uint32_t*)(d + i + 2) = packbf(v.z, v.w);
}

// ---------------------------------------------------------------------------
// bf16 GEMM: C[m,n] = sum_k A[m,k] * B[n,k]
// CTA 128x128, kstep 32, 256 thr = 8 warps (4m x 2n), warp 32x64, m16n8k16.
// mode (RUNTIME, epilogue-only): 0 bf16 out; 1 e4m3 out; 2 fp32 out + residual.
// Single instantiation per kernel -> one set of static smem arrays (40 KB).
// ---------------------------------------------------------------------------
static __device__ __forceinline__ void bgemm_body(
    const __nv_bfloat16* __restrict__ Ag, const __nv_bfloat16* __restrict__ Bg,
    __nv_bfloat16* __restrict__ Cb, uint8_t* __restrict__ C8,
    float* __restrict__ Cf, const float* __restrict__ resid, int mode)
{
    __shared__ __nv_bfloat16 As[2][128 * 40];
    __shared__ __nv_bfloat16 Bs[2][128 * 40];

    const int tid = threadIdx.x;
    const int wid = tid >> 5, lane = tid & 31;
    const int g = lane >> 2, tc = lane & 3;
    const int wr = wid & 3, wn = wid >> 2;
    const int m0 = blockIdx.y * 128, n0 = blockIdx.x * 128;

    const uint32_t as0 = s2u(As[0]), as1 = s2u(As[1]);
    const uint32_t bs0 = s2u(Bs[0]), bs1 = s2u(Bs[1]);

    {
#pragma unroll
        for (int i = 0; i < 2; i++) {
            const int idx = tid + i * 256;
            const int r = idx >> 2, c = idx & 3;
            cpa16(as0 + r * 80 + c * 16, Ag + (size_t)(m0 + r) * NDIM + c * 8);
            cpa16(bs0 + r * 80 + c * 16, Bg + (size_t)(n0 + r) * NDIM + c * 8);
        }
        cpa_commit();
    }

    float cacc[2][8][4];
#pragma unroll
    for (int mi = 0; mi < 2; mi++)
#pragma unroll
        for (int ni = 0; ni < 8; ni++)
#pragma unroll
            for (int c = 0; c < 4; c++) cacc[mi][ni][c] = 0.f;

    for (int kb = 0; kb < 16; kb++) {
        cpa_wait0();
        __syncthreads();
        if (kb < 15) {
            const int k0 = (kb + 1) * 32;
            const uint32_t as = (kb & 1) ? as0 : as1;
            const uint32_t bs = (kb & 1) ? bs0 : bs1;
#pragma unroll
            for (int i = 0; i < 2; i++) {
                const int idx = tid + i * 256;
                const int r = idx >> 2, c = idx & 3;
                cpa16(as + r * 80 + c * 16, Ag + (size_t)(m0 + r) * NDIM + k0 + c * 8);
                cpa16(bs + r * 80 + c * 16, Bg + (size_t)(n0 + r) * NDIM + k0 + c * 8);
            }
            cpa_commit();
        }
        const uint32_t* Aw = (const uint32_t*)As[kb & 1];
        const uint32_t* Bw = (const uint32_t*)Bs[kb & 1];

#pragma unroll
        for (int h = 0; h < 2; h++) {
            const int kw = h * 8;
            uint32_t a[2][4];
#pragma unroll
            for (int mi = 0; mi < 2; mi++) {
                const int row = wr * 32 + mi * 16 + g;
                a[mi][0] = Aw[row * 20 + kw + tc];
                a[mi][1] = Aw[(row + 8) * 20 + kw + tc];
                a[mi][2] = Aw[row * 20 + kw + tc + 4];
                a[mi][3] = Aw[(row + 8) * 20 + kw + tc + 4];
            }
#pragma unroll
            for (int ni = 0; ni < 8; ni++) {
                const int br = wn * 64 + ni * 8 + g;
                const uint32_t b0 = Bw[br * 20 + kw + tc];
                const uint32_t b1 = Bw[br * 20 + kw + tc + 4];
                MMA_BF16(cacc[0][ni], a[0], b0, b1);
                MMA_BF16(cacc[1][ni], a[1], b0, b1);
            }
        }
    }

#pragma unroll
    for (int mi = 0; mi < 2; mi++) {
        const int row = m0 + wr * 32 + mi * 16 + g;
#pragma unroll
        for (int ni = 0; ni < 8; ni++) {
            const int col = n0 + wn * 64 + ni * 8 + tc * 2;
            if (mode == 2) {
                const float2 x0 = *(const float2*)(resid + (size_t)row * NDIM + col);
                const float2 x1 = *(const float2*)(resid + (size_t)(row + 8) * NDIM + col);
                *(float2*)(Cf + (size_t)row * NDIM + col) =
                    make_float2(cacc[mi][ni][0] + x0.x, cacc[mi][ni][1] + x0.y);
                *(float2*)(Cf + (size_t)(row + 8) * NDIM + col) =
                    make_float2(cacc[mi][ni][2] + x1.x, cacc[mi][ni][3] + x1.y);
            } else if (mode == 1) {
                *(uint16_t*)(C8 + (size_t)row * NDIM + col) =
                    packf8(cacc[mi][ni][0], cacc[mi][ni][1]);
                *(uint16_t*)(C8 + (size_t)(row + 8) * NDIM + col) =
                    packf8(cacc[mi][ni][2], cacc[mi][ni][3]);
            } else {
                *(uint32_t*)(Cb + (size_t)row * NDIM + col) =
                    packbf(cacc[mi][ni][0], cacc[mi][ni][1]);
                *(uint32_t*)(Cb + (size_t)(row + 8) * NDIM + col) =
                    packbf(cacc[mi][ni][2], cacc[mi][ni][3]);
            }
        }
    }
}

__global__ void __launch_bounds__(256) qkv_bgemm_kernel()
{
    const int z = blockIdx.z;
    const __nv_bfloat16* B = (z == 0) ? g_Wqb : (z == 1) ? g_Wkb : g_Wvb;
    uint8_t* C8 = (z == 0) ? g_Q8 : g_K8;
    const int mode = (z == 2) ? 0 : 1;
    bgemm_body(g_xb, B, g_V, C8, nullptr, nullptr, mode);
}

__global__ void __launch_bounds__(256) oproj_bgemm_kernel(const float* __restrict__ x,
                                                          float* __restrict__ out)
{
    bgemm_body(g_AO, g_Wob, nullptr, nullptr, out, x, 2);
}

// ---------------------------------------------------------------------------
// flash attention: S = QK^T in e4m3 (m16n8k32), PV in bf16 (m16n8k16).
// CTA = 128 q x one (b,h), 256 thr = 8 warps (4 q-row x 2 kv-half).
// Unnormalized streaming softmax: P = exp2(0.1803·S) (0.125 scale folded in).
// Q/K tiles: 128 rows x 64B fp8, padded to 80B. V: 128 x 128B bf16 pad 144B.
// ---------------------------------------------------------------------------
#define Q_SW   20        // words per fp8 row (80 B)
#define Q_ROWB 80
#define V_ROWB 144
#define OQ  0
#define OK0 10240
#define OK1 20480
#define OV0 30720
#define OV1 49152
#define OLS 67584
#define ATT_SMEM (OLS + 1024)
#define EXPC 0.18033688f   // 0.125 * log2(e)

static __device__ __forceinline__ void ld_tile_f8(uint32_t dst,
                                                  const uint8_t* src,
                                                  int row0, int tid)
{
#pragma unroll
    for (int i = 0; i < 2; i++) {
        const int idx = tid + i * 256;
        const int r = idx >> 2, c = idx & 3;
        cpa16(dst + r * Q_ROWB + c * 16, src + (size_t)(row0 + r) * NDIM + c * 16);
    }
}
static __device__ __forceinline__ void ld_tile_v(uint32_t dst,
                                                 const __nv_bfloat16* src,
                                                 int row0, int tid)
{
#pragma unroll
    for (int i = 0; i < 4; i++) {
        const int idx = tid + i * 256;
        const int r = idx >> 3, c = idx & 7;
        cpa16(dst + r * V_ROWB + c * 16, src + (size_t)(row0 + r) * NDIM + c * 8);
    }
}

__global__ void __launch_bounds__(256, 1) attn_kernel()
{
    extern __shared__ char smc[];
    const uint32_t smb = s2u(smc);

    const int tid  = threadIdx.x;
    const int wid  = tid >> 5;
    const int lane = tid & 31;
    const int wr = wid & 3;          // q-row block (32 rows)
    const int wc = wid >> 2;         // kv-half (64 cols)
    const int g  = lane >> 2;
    const int tc = lane & 3;

    const int q0 = blockIdx.x * 128;
    const int bh = blockIdx.y;
    const int b  = bh >> 3;
    const int h  = bh & 7;

    const uint8_t* Qg = g_Q8 + (size_t)b * SEQ * NDIM + h * DH;
    const uint8_t* Kg = g_K8 + (size_t)b * SEQ * NDIM + h * DH;
    const __nv_bfloat16* Vg = g_V + (size_t)b * SEQ * NDIM + h * DH;

    float* ls = (float*)(smc + OLS);
    ls[tid] = 0.f;

    ld_tile_f8(smb + OQ,  Qg, q0, tid);
    ld_tile_f8(smb + OK0, Kg, 0,  tid);
    ld_tile_v (smb + OV0, Vg, 0,  tid);
    cpa_commit();
    cpa_wait0();
    __syncthreads();

    // hoist Q fragments (2 k32-steps x 2 mi x 4 regs)
    uint32_t qfr[2][2][4];
    {
        const uint32_t* Qw = (const uint32_t*)smc;
#pragma unroll
        for (int ks = 0; ks < 2; ks++)
#pragma unroll
            for (int mi = 0; mi < 2; mi++) {
                const int row = wr * 32 + mi * 16 + g;
                qfr[ks][mi][0] = Qw[row * Q_SW + ks * 8 + tc];
                qfr[ks][mi][1] = Qw[(row + 8) * Q_SW + ks * 8 + tc];
                qfr[ks][mi][2] = Qw[row * Q_SW + ks * 8 + tc + 4];
                qfr[ks][mi][3] = Qw[(row + 8) * Q_SW + ks * 8 + tc + 4];
            }
    }

    float oacc[2][8][4];
#pragma unroll
    for (int mi = 0; mi < 2; mi++)
#pragma unroll
        for (int nd = 0; nd < 8; nd++)
#pragma unroll
            for (int c = 0; c < 4; c++) oacc[mi][nd][c] = 0.f;

    const int mat = lane >> 3, lr = lane & 7;

    for (int j = 0; j < NT; j++) {
        if (j + 1 < NT) {
            const int nb = (j + 1) & 1;
            ld_tile_f8(smb + (nb ? OK1 : OK0), Kg, (j + 1) * 128, tid);
            ld_tile_v (smb + (nb ? OV1 : OV0), Vg, (j + 1) * 128, tid);
            cpa_commit();
        }

        // ---- S = Q K^T (fp8, 2 k32-steps) ----
        const uint32_t* Kw = (const uint32_t*)(smc + ((j & 1) ? OK1 : OK0));
        float sacc[2][8][4];
#pragma unroll
        for (int mi = 0; mi < 2; mi++)
#pragma unroll
            for (int ni = 0; ni < 8; ni++)
#pragma unroll
                for (int c = 0; c < 4; c++) sacc[mi][ni][c] = 0.f;

#pragma unroll
        for (int ks = 0; ks < 2; ks++) {
#pragma unroll
            for (int ni = 0; ni < 8; ni++) {
                const int br = wc * 64 + ni * 8 + g;
                const uint32_t b0 = Kw[br * Q_SW + ks * 8 + tc];
                const uint32_t b1 = Kw[br * Q_SW + ks * 8 + tc + 4];
                MMA_FP8(sacc[0][ni], qfr[ks][0], b0, b1);
                MMA_FP8(sacc[1][ni], qfr[ks][1], b0, b1);
            }
        }

        // ---- softmax (unnormalized, scale folded): exp2, row-sum, pack bf16 ----
        uint32_t pfr[2][8][2];
        float rs[2][2] = {{0.f, 0.f}, {0.f, 0.f}};
#pragma unroll
        for (int mi = 0; mi < 2; mi++)
#pragma unroll
            for (int ni = 0; ni < 8; ni++) {
                const float e0 = exp2f(sacc[mi][ni][0] * EXPC);
                const float e1 = exp2f(sacc[mi][ni][1] * EXPC);
                const float e2 = exp2f(sacc[mi][ni][2] * EXPC);
                const float e3 = exp2f(sacc[mi][ni][3] * EXPC);
                rs[mi][0] += e0 + e1;
                rs[mi][1] += e2 + e3;
                pfr[mi][ni][0] = packbf(e0, e1);
                pfr[mi][ni][1] = packbf(e2, e3);
            }
#pragma unroll
        for (int mi = 0; mi < 2; mi++)
#pragma unroll
            for (int hh = 0; hh < 2; hh++) {
                float r = rs[mi][hh];
                r += __shfl_xor_sync(0xffffffffu, r, 1);
                r += __shfl_xor_sync(0xffffffffu, r, 2);
                rs[mi][hh] = r;
            }
        if (tc == 0) {
            float* l = ls + wc * 128 + wr * 32;
#pragma unroll
            for (int mi = 0; mi < 2; mi++) {
                l[mi * 16 + g]     += rs[mi][0];
                l[mi * 16 + 8 + g] += rs[mi][1];
            }
        }

        // ---- O += P V (bf16; warp's kv-half, k=64 -> 4 k16-steps) ----
        const uint32_t vbase = smb + ((j & 1) ? OV1 : OV0);
#pragma unroll
        for (int ki = 0; ki < 4; ki++) {
            uint32_t bfr[8][2];
#pragma unroll
            for (int db = 0; db < 4; db++) {
                const uint32_t addr = vbase +
                    (uint32_t)(wc * 64 + ki * 16 + (mat & 1) * 8 + lr) * V_ROWB +
                    (uint32_t)(db * 16 + (mat >> 1) * 8) * 2;
                LDSM_X4_T(bfr[db * 2][0], bfr[db * 2][1],
                          bfr[db * 2 + 1][0], bfr[db * 2 + 1][1], addr);
            }
#pragma unroll
            for (int mi = 0; mi < 2; mi++) {
                uint32_t a[4] = { pfr[mi][2 * ki][0],     pfr[mi][2 * ki][1],
                                  pfr[mi][2 * ki + 1][0], pfr[mi][2 * ki + 1][1] };
#pragma unroll
                for (int nd = 0; nd < 8; nd++)
                    MMA_BF16(oacc[mi][nd], a, bfr[nd][0], bfr[nd][1]);
            }
        }

        if (j + 1 < NT) {
            cpa_wait0();
            __syncthreads();
        }
    }

    // ---- epilogue: combine kv-halves in smem, normalize, store bf16 ----
    __syncthreads();
    float* Osm = (float*)(smc + OK0);   // 128 x 64, stride 68 floats
    if (wc == 0) {
#pragma unroll
        for (int mi = 0; mi < 2; mi++) {
            const int r0 = wr * 32 + mi * 16 + g;
#pragma unroll
            for (int nd = 0; nd < 8; nd++) {
                const int col = nd * 8 + tc * 2;
                Osm[r0 * 68 + col]           = oacc[mi][nd][0];
                Osm[r0 * 68 + col + 1]       = oacc[mi][nd][1];
                Osm[(r0 + 8) * 68 + col]     = oacc[mi][nd][2];
                Osm[(r0 + 8) * 68 + col + 1] = oacc[mi][nd][3];
            }
        }
    }
    __syncthreads();
    if (wc == 1) {
#pragma unroll
        for (int mi = 0; mi < 2; mi++) {
            const int r0 = wr * 32 + mi * 16 + g;
#pragma unroll
            for (int nd = 0; nd < 8; nd++) {
                const int col = nd * 8 + tc * 2;
                Osm[r0 * 68 + col]           += oacc[mi][nd][0];
                Osm[r0 * 68 + col + 1]       += oacc[mi][nd][1];
                Osm[(r0 + 8) * 68 + col]     += oacc[mi][nd][2];
                Osm[(r0 + 8) * 68 + col + 1] += oacc[mi][nd][3];
            }
        }
    }
    __syncthreads();

    const int row = tid >> 1;
    const int c0  = (tid & 1) * 32;
    const float inv = 1.f / (ls[row] + ls[128 + row]);
    __nv_bfloat16* Og = g_AO + (size_t)b * SEQ * NDIM +
                        (size_t)(q0 + row) * NDIM + h * DH + c0;
#pragma unroll
    for (int c = 0; c < 32; c += 2)
        *(uint32_t*)(Og + c) = packbf(Osm[row * 68 + c0 + c] * inv,
                                      Osm[row * 68 + c0 + c + 1] * inv);
}

// ---------------------------------------------------------------------------
extern "C" void kernel_launch(void* const* d_in, const int* in_sizes, int n_in,
                              void* d_out, int out_size)
{
    const float* x  = (const float*)d_in[0];
    const float* Wq = (const float*)d_in[1];
    const float* Wk = (const float*)d_in[2];
    const float* Wv = (const float*)d_in[3];
    const float* Wo = (const float*)d_in[4];
    float* out = (float*)d_out;

    __nv_bfloat16* dxb;
    cudaGetSymbolAddress((void**)&dxb, g_xb);

    cudaFuncSetAttribute(attn_kernel,
                         cudaFuncAttributeMaxDynamicSharedMemorySize, ATT_SMEM);

    cvt_kernel<<<(MTOT * NDIM) / 1024, 256>>>(x, dxb);
    dim3 gw((NDIM * NDIM) / 1024, 1, 4);
    cvtw_kernel<<<gw, 256>>>(Wq, Wk, Wv, Wo);

    dim3 gqkv(NDIM / 128, MTOT / 128, 3);
    qkv_bgemm_kernel<<<gqkv, 256>>>();

    dim3 gattn(SEQ / 128, 16);
    attn_kernel<<<gattn, 256, ATT_SMEM>>>();

    dim3 go(NDIM / 128, MTOT / 128);
    oproj_bgemm_kernel<<<go, 256>>>(x, out);
}